// round 2
// baseline (speedup 1.0000x reference)
#include <cuda_runtime.h>
#include <cstdint>

#define MARGIN 0.1f
#define TPB 256
#define EPT 8          // elements per thread: TPB*EPT = 2048 = L
#define MAX_B 32768

// Per-row partial results: x = per_sample contribution (0 if invalid), y = valid flag
__device__ float2 g_partial[MAX_B];

__global__ void __launch_bounds__(TPB) hinge_row_kernel(
    const float* __restrict__ scores,
    const int* __restrict__ lens,
    const int* __restrict__ labels,
    int L)
{
    const int row = blockIdx.x;
    const int len = lens[row];
    const size_t base = (size_t)row * (size_t)L;
    const float* __restrict__ srow = scores + base;
    const int* __restrict__ lrow = labels + base;
    const int t = threadIdx.x;

    float s[EPT];
    bool isNeg[EPT];

    float pos_sum = 0.0f;
    int pos_cnt = 0;

#pragma unroll
    for (int k = 0; k < EPT; k++) {
        const int j = t + k * TPB;
        float sv = 0.0f;
        int lv = -1;
        if (j < L) {
            sv = srow[j];
            lv = lrow[j];
        }
        const bool valid = (j < L) && (j < len);
        const bool p = valid && (lv == 1);
        const bool n = valid && (lv == 0);
        s[k] = sv;
        isNeg[k] = n;
        if (p) { pos_sum += sv; pos_cnt++; }
    }

    // ---- block reduce pos_sum / pos_cnt ----
    __shared__ float sh_f[TPB / 32];
    __shared__ int   sh_i[TPB / 32];
    __shared__ float sh_chosen;

#pragma unroll
    for (int o = 16; o > 0; o >>= 1) {
        pos_sum += __shfl_down_sync(0xFFFFFFFFu, pos_sum, o);
        pos_cnt += __shfl_down_sync(0xFFFFFFFFu, pos_cnt, o);
    }
    const int wid = t >> 5, lid = t & 31;
    if (lid == 0) { sh_f[wid] = pos_sum; sh_i[wid] = pos_cnt; }
    __syncthreads();
    if (t == 0) {
        float ps = 0.0f; int pc = 0;
#pragma unroll
        for (int w = 0; w < TPB / 32; w++) { ps += sh_f[w]; pc += sh_i[w]; }
        sh_chosen = (pc > 0) ? ps : -MARGIN;
    }
    __syncthreads();
    const float chosen = sh_chosen;

    // ---- hinge over negatives, from register-resident scores ----
    float hs = 0.0f;
    int nc = 0;
#pragma unroll
    for (int k = 0; k < EPT; k++) {
        if (isNeg[k]) {
            hs += fmaxf(MARGIN + s[k] - chosen, 0.0f);
            nc++;
        }
    }
#pragma unroll
    for (int o = 16; o > 0; o >>= 1) {
        hs += __shfl_down_sync(0xFFFFFFFFu, hs, o);
        nc += __shfl_down_sync(0xFFFFFFFFu, nc, o);
    }
    __syncthreads();   // shared reuse barrier
    if (lid == 0) { sh_f[wid] = hs; sh_i[wid] = nc; }
    __syncthreads();
    if (t == 0) {
        float h = 0.0f; int n = 0;
#pragma unroll
        for (int w = 0; w < TPB / 32; w++) { h += sh_f[w]; n += sh_i[w]; }
        float contrib = 0.0f, flag = 0.0f;
        if (len > 0 && n > 0) {        // valid_obs = (len>0) & has_neg
            contrib = h / (float)n;    // per_sample (neg_cnt >= 1 here)
            flag = 1.0f;
        }
        g_partial[row] = make_float2(contrib, flag);
    }
}

__global__ void __launch_bounds__(1024) hinge_reduce_kernel(float* __restrict__ out, int B)
{
    float tot = 0.0f, cnt = 0.0f;
    for (int i = threadIdx.x; i < B; i += blockDim.x) {
        const float2 p = g_partial[i];
        tot += p.x;
        cnt += p.y;
    }
#pragma unroll
    for (int o = 16; o > 0; o >>= 1) {
        tot += __shfl_down_sync(0xFFFFFFFFu, tot, o);
        cnt += __shfl_down_sync(0xFFFFFFFFu, cnt, o);
    }
    __shared__ float sf[32], sc[32];
    const int wid = threadIdx.x >> 5, lid = threadIdx.x & 31;
    if (lid == 0) { sf[wid] = tot; sc[wid] = cnt; }
    __syncthreads();
    if (threadIdx.x == 0) {
        float T = 0.0f, C = 0.0f;
        const int nw = blockDim.x >> 5;
        for (int w = 0; w < nw; w++) { T += sf[w]; C += sc[w]; }
        out[0] = (C > 0.0f) ? (T / fmaxf(C, 1.0f)) : 0.0f;
    }
}

extern "C" void kernel_launch(void* const* d_in, const int* in_sizes, int n_in,
                              void* d_out, int out_size)
{
    const float* scores   = (const float*)d_in[0];
    const int*   lens     = (const int*)d_in[1];
    const int*   labels   = (const int*)d_in[2];
    float* out = (float*)d_out;

    const int B = in_sizes[1];            // candidate_lengths element count
    const int L = in_sizes[0] / B;        // 2048

    hinge_row_kernel<<<B, TPB>>>(scores, lens, labels, L);
    hinge_reduce_kernel<<<1, 1024>>>(out, B);
}

// round 3
// speedup vs baseline: 1.3803x; 1.3803x over previous
#include <cuda_runtime.h>
#include <cstdint>

#define MARGIN 0.1f
#define TPB 256
#define VPT 2           // float4 vectors per thread: TPB*VPT*4 = 2048 = L
#define EPT (VPT * 4)

// Global accumulators (zeroed by init kernel each launch)
__device__ float g_total;
__device__ float g_count;

__global__ void hinge_init_kernel()
{
    g_total = 0.0f;
    g_count = 0.0f;
}

__global__ void __launch_bounds__(TPB) hinge_row_kernel(
    const float* __restrict__ scores,
    const int* __restrict__ lens,
    const int* __restrict__ labels,
    int L)
{
    const int row = blockIdx.x;
    const int len = lens[row];
    const size_t base = (size_t)row * (size_t)L;
    const float4* __restrict__ srow = (const float4*)(scores + base);
    const int4*   __restrict__ lrow = (const int4*)(labels + base);
    const int t = threadIdx.x;
    const int L4 = L >> 2;

    float s[EPT];
    bool isNeg[EPT];

    float pos_sum = 0.0f;
    int pos_cnt = 0;

#pragma unroll
    for (int k = 0; k < VPT; k++) {
        const int v = t + k * TPB;
        float4 sv = make_float4(0.f, 0.f, 0.f, 0.f);
        int4   lv = make_int4(-1, -1, -1, -1);
        if (v < L4) {
            sv = srow[v];
            lv = lrow[v];
        }
        const int j0 = v << 2;
        const float se[4] = { sv.x, sv.y, sv.z, sv.w };
        const int   le[4] = { lv.x, lv.y, lv.z, lv.w };
#pragma unroll
        for (int e = 0; e < 4; e++) {
            const int j = j0 + e;
            const bool valid = (j < L) && (j < len);
            const bool p = valid && (le[e] == 1);
            const bool n = valid && (le[e] == 0);
            s[k * 4 + e] = se[e];
            isNeg[k * 4 + e] = n;
            if (p) { pos_sum += se[e]; pos_cnt++; }
        }
    }

    // ---- block reduce pos_sum / pos_cnt ----
    __shared__ float sh_f[TPB / 32];
    __shared__ int   sh_i[TPB / 32];
    __shared__ float sh_chosen;

#pragma unroll
    for (int o = 16; o > 0; o >>= 1) {
        pos_sum += __shfl_down_sync(0xFFFFFFFFu, pos_sum, o);
        pos_cnt += __shfl_down_sync(0xFFFFFFFFu, pos_cnt, o);
    }
    const int wid = t >> 5, lid = t & 31;
    if (lid == 0) { sh_f[wid] = pos_sum; sh_i[wid] = pos_cnt; }
    __syncthreads();
    if (t == 0) {
        float ps = 0.0f; int pc = 0;
#pragma unroll
        for (int w = 0; w < TPB / 32; w++) { ps += sh_f[w]; pc += sh_i[w]; }
        sh_chosen = (pc > 0) ? ps : -MARGIN;
    }
    __syncthreads();
    const float chosen = sh_chosen;

    // ---- hinge over negatives, from register-resident scores ----
    float hs = 0.0f;
    int nc = 0;
#pragma unroll
    for (int k = 0; k < EPT; k++) {
        if (isNeg[k]) {
            hs += fmaxf(MARGIN + s[k] - chosen, 0.0f);
            nc++;
        }
    }
#pragma unroll
    for (int o = 16; o > 0; o >>= 1) {
        hs += __shfl_down_sync(0xFFFFFFFFu, hs, o);
        nc += __shfl_down_sync(0xFFFFFFFFu, nc, o);
    }
    __syncthreads();   // shared reuse barrier
    if (lid == 0) { sh_f[wid] = hs; sh_i[wid] = nc; }
    __syncthreads();
    if (t == 0) {
        float h = 0.0f; int n = 0;
#pragma unroll
        for (int w = 0; w < TPB / 32; w++) { h += sh_f[w]; n += sh_i[w]; }
        if (len > 0 && n > 0) {              // valid_obs = (len>0) & has_neg
            atomicAdd(&g_total, h / (float)n);
            atomicAdd(&g_count, 1.0f);
        }
    }
}

__global__ void hinge_final_kernel(float* __restrict__ out)
{
    const float T = g_total;
    const float C = g_count;
    out[0] = (C > 0.0f) ? (T / fmaxf(C, 1.0f)) : 0.0f;
}

extern "C" void kernel_launch(void* const* d_in, const int* in_sizes, int n_in,
                              void* d_out, int out_size)
{
    const float* scores = (const float*)d_in[0];
    const int*   lens   = (const int*)d_in[1];
    const int*   labels = (const int*)d_in[2];
    float* out = (float*)d_out;

    const int B = in_sizes[1];            // candidate_lengths element count
    const int L = in_sizes[0] / B;        // 2048

    hinge_init_kernel<<<1, 1>>>();
    hinge_row_kernel<<<B, TPB>>>(scores, lens, labels, L);
    hinge_final_kernel<<<1, 1>>>(out);
}